// round 5
// baseline (speedup 1.0000x reference)
#include <cuda_runtime.h>
#include <cuda_fp16.h>
#include <cstdint>

#define B_  256
#define T_  1024
#define H_  256

#define MT 32       // batch rows per group
#define NT 128      // permuted gate cols per CTA (32 hidden units x 4 gates)
#define NGROUP 8
#define NTILE  8
#define THREADS 256
#define CLUSTER 8

#define RSH 264               // hbuf / As row stride in halfs
#define HB_HALF (MT * RSH)    // 8448 halfs = 16896 B per buffer
#define HB_BUFB 16896
#define GS  132               // gate dump row stride (floats)
#define RS1 520               // L1 weight row stride (halfs)

// dynamic smem layout (bytes)
#define HB_OFF   0
#define GS_OFF   33792                     // 2 * HB_BUFB
#define BIAS_OFF (GS_OFF + MT * GS * 4)    // 50688
#define WX_OFF   (BIAS_OFF + NT * 4)       // 51200
#define XS_OFF   (WX_OFF + NT * 4)         // 51712
#define MBAR_OFF (XS_OFF + 2 * MT * 4)     // 51968
#define WS_OFF   52224
#define AS_OFF   (WS_OFF + NT * RS1 * 2)   // 185344
#define SMEM_TOTAL (AS_OFF + 2 * HB_BUFB)  // 219136

#define TX_BYTES 16384u   // 8 CTAs x 256 threads x 8 B per step

// -------- persistent device scratch --------
__device__ __half   g_y0[(size_t)T_ * B_ * H_];   // layer-0 outputs [T][B][H]
__device__ unsigned g_ctr0[NGROUP];

__global__ void init_kernel() {
    if (threadIdx.x < NGROUP) g_ctr0[threadIdx.x] = 0u;
}

// -------- helpers --------
__device__ __forceinline__ uint32_t smem_u32(const void* p) {
    return (uint32_t)__cvta_generic_to_shared(p);
}
__device__ __forceinline__ unsigned ld_acq(const unsigned* p) {
    unsigned v;
    asm volatile("ld.acquire.gpu.global.u32 %0, [%1];" : "=r"(v) : "l"(p) : "memory");
    return v;
}
__device__ __forceinline__ void red_add_rel(unsigned* p) {
    asm volatile("red.release.gpu.global.add.u32 [%0], 1;" :: "l"(p) : "memory");
}
__device__ __forceinline__ float tanh_hw(float x) {
    float y;
    asm("tanh.approx.f32 %0, %1;" : "=f"(y) : "f"(x));
    return y;
}
__device__ __forceinline__ float sig_hw(float x) {
    return fmaf(0.5f, tanh_hw(0.5f * x), 0.5f);
}
__device__ __forceinline__ void mma16816(float* d, const uint32_t* a, uint32_t b0, uint32_t b1) {
    asm volatile(
        "mma.sync.aligned.m16n8k16.row.col.f32.f16.f16.f32 "
        "{%0,%1,%2,%3}, {%4,%5,%6,%7}, {%8,%9}, {%0,%1,%2,%3};\n"
        : "+f"(d[0]), "+f"(d[1]), "+f"(d[2]), "+f"(d[3])
        : "r"(a[0]), "r"(a[1]), "r"(a[2]), "r"(a[3]), "r"(b0), "r"(b1));
}
__device__ __forceinline__ void ldsm4(uint32_t* r, uint32_t addr) {
    asm volatile("ldmatrix.sync.aligned.m8n8.x4.shared.b16 {%0,%1,%2,%3}, [%4];"
        : "=r"(r[0]), "=r"(r[1]), "=r"(r[2]), "=r"(r[3]) : "r"(addr));
}
__device__ __forceinline__ uint32_t mapa_u32(uint32_t addr, uint32_t rank) {
    uint32_t r;
    asm("mapa.shared::cluster.u32 %0, %1, %2;" : "=r"(r) : "r"(addr), "r"(rank));
    return r;
}
__device__ __forceinline__ void st_async_u64(uint32_t daddr, uint64_t v, uint32_t mbar) {
    asm volatile(
        "st.async.shared::cluster.mbarrier::complete_tx::bytes.u64 [%0], %1, [%2];"
        :: "r"(daddr), "l"(v), "r"(mbar) : "memory");
}
__device__ __forceinline__ void mbar_init(uint32_t a, uint32_t cnt) {
    asm volatile("mbarrier.init.shared.b64 [%0], %1;" :: "r"(a), "r"(cnt) : "memory");
}
__device__ __forceinline__ void mbar_expect(uint32_t a, uint32_t bytes) {
    asm volatile("mbarrier.arrive.expect_tx.shared.b64 _, [%0], %1;"
                 :: "r"(a), "r"(bytes) : "memory");
}
__device__ __forceinline__ void mbar_wait(uint32_t a, uint32_t par) {
    uint32_t done = 0;
    while (!done) {
        asm volatile(
            "{\n\t.reg .pred p;\n\t"
            "mbarrier.try_wait.parity.acquire.cluster.shared::cta.b64 p, [%1], %2;\n\t"
            "selp.b32 %0, 1, 0, p;\n\t}"
            : "=r"(done) : "r"(a), "r"(par) : "memory");
    }
}
__device__ __forceinline__ void cluster_sync() {
    asm volatile("barrier.cluster.arrive.aligned;" ::: "memory");
    asm volatile("barrier.cluster.wait.aligned;" ::: "memory");
}

// ====================================================================
// One persistent LSTM layer; one 8-CTA cluster per batch group.
// Gate cols permuted: perm col n -> original row (n&3)*H + (n>>2).
// h is exchanged via DSMEM st.async into every peer's smem hbuf,
// synchronized by a transaction mbarrier (expect 16KB per step).
//   L0: gates = h @ Whh^T (+ x*wih + bias), Whh in registers
//   L1: gates = [y0_t | h] @ [Wih;Whh]^T + bias; y0 half of the GEMM
//       runs BEFORE the h wait (no h dependency).
// ====================================================================
template <bool IS_L0>
__device__ __forceinline__ void run_layer(const float* __restrict__ x,
                                          const float* __restrict__ Wih,
                                          const float* __restrict__ Whh,
                                          const float* __restrict__ bih,
                                          const float* __restrict__ bhh,
                                          float* __restrict__ out,
                                          int layer_idx) {
    extern __shared__ char sm[];
    const uint32_t smb = smem_u32(sm);

    __half* hbufs  = (__half*)(sm + HB_OFF);
    float*  Gs     = (float*)(sm + GS_OFF);
    float*  bias_s = (float*)(sm + BIAS_OFF);
    float*  wx_s   = (float*)(sm + WX_OFF);
    float*  xs     = (float*)(sm + XS_OFF);
    const uint32_t mb_local = smb + MBAR_OFF;
    __half* Ws = (__half*)(sm + WS_OFF);
    __half* As = (__half*)(sm + AS_OFF);

    const int tid  = threadIdx.x;
    const int lane = tid & 31, warp = tid >> 5;
    const int gid  = lane >> 2, tig = lane & 3;
    const int ntile = blockIdx.x, grp = blockIdx.y;
    const int n0 = ntile * NT;
    const int b0 = grp * MT;
    const int j0 = n0 >> 2;

    // ---- mbarriers + zero hbuf, then cluster-wide visibility ----
    if (tid == 0) { mbar_init(mb_local, 1); mbar_init(mb_local + 8, 1); }
    for (int i = tid; i < 2 * HB_BUFB / 16; i += THREADS)
        ((uint4*)hbufs)[i] = make_uint4(0, 0, 0, 0);
    __syncthreads();
    cluster_sync();

    // ---- one-time: bias (+ scalar input weight for L0) ----
    if (tid < NT) {
        int n_g = n0 + tid;
        int p   = (n_g & 3) * H_ + (n_g >> 2);
        bias_s[tid] = bih[p] + bhh[p];
        if (IS_L0) wx_s[tid] = Wih[p];
    }

    // ---- one-time: weights ----
    uint32_t bw[2][16][2];
    if constexpr (IS_L0) {
        #pragma unroll
        for (int ni = 0; ni < 2; ni++) {
            int n_g = n0 + warp * 16 + ni * 8 + gid;
            int p   = (n_g & 3) * H_ + (n_g >> 2);
            const float* wr = Whh + (size_t)p * H_;
            #pragma unroll
            for (int kc = 0; kc < 16; kc++) {
                int k = kc * 16 + tig * 2;
                __half2 h01 = __floats2half2_rn(wr[k], wr[k + 1]);
                __half2 h89 = __floats2half2_rn(wr[k + 8], wr[k + 9]);
                bw[ni][kc][0] = *(uint32_t*)&h01;
                bw[ni][kc][1] = *(uint32_t*)&h89;
            }
        }
        if (tid < MT) xs[tid] = x[(size_t)(b0 + tid) * T_];
        __syncthreads();
    } else {
        for (int idx = tid; idx < NT * 512; idx += THREADS) {
            int nl = idx >> 9, k = idx & 511;
            int n_g = n0 + nl;
            int p   = (n_g & 3) * H_ + (n_g >> 2);
            float v = (k < H_) ? Wih[(size_t)p * H_ + k]
                               : Whh[(size_t)p * H_ + (k - H_)];
            Ws[nl * RS1 + k] = __float2half_rn(v);
        }
        // prologue: wait for y0[0], load into As buf 0
        if (tid == 0) { while (ld_acq(g_ctr0 + grp) < (unsigned)NTILE) { } }
        __syncthreads();
        {
            int row = tid >> 3, seg = tid & 7;
            const uint4* src = (const uint4*)(g_y0 + (size_t)(b0 + row) * H_ + seg * 32);
            uint4* dst = (uint4*)(As + row * RSH + seg * 32);
            #pragma unroll
            for (int i = 0; i < 4; i++) dst[i] = src[i];
        }
        __syncthreads();
    }

    // ---- per-thread DSMEM destinations (all 8 cluster ranks) ----
    const uint32_t my_slot = smb + HB_OFF +
        (uint32_t)(((tid >> 3) * RSH + j0 + (tid & 7) * 4) * 2);
    uint32_t dstB[CLUSTER], mbB[CLUSTER];
    #pragma unroll
    for (int r = 0; r < CLUSTER; r++) {
        dstB[r] = mapa_u32(my_slot, r);
        mbB[r]  = mapa_u32(mb_local, r);
    }

    // ---- ldsm fragment offsets ----
    const uint32_t aoff0 = (uint32_t)((((lane & 15)) * RSH + ((lane >> 4) & 1) * 8) * 2);
    const uint32_t aoff1 = aoff0 + (uint32_t)(16 * RSH * 2);
    uint32_t bAddr = 0;
    if constexpr (!IS_L0) {
        int rB = warp * 16 + (lane & 7) + ((lane & 16) ? 8 : 0);
        int cB = (lane & 8) ? 8 : 0;
        bAddr = smb + WS_OFF + (uint32_t)((rB * RS1 + cB) * 2);
    }

    const int m     = tid >> 3;
    const int ubase = (tid & 7) * 4;
    float creg[4] = {0.f, 0.f, 0.f, 0.f};

    for (int t = 0; t < T_; ++t) {
        const int cb = t & 1, nb = (t + 1) & 1;
        if (tid == 0 && t + 1 < T_) mbar_expect(mb_local + nb * 8, TX_BYTES);

        float acc[2][2][4];
        #pragma unroll
        for (int mi = 0; mi < 2; mi++)
            #pragma unroll
            for (int ni = 0; ni < 2; ni++)
                #pragma unroll
                for (int r = 0; r < 4; r++) acc[mi][ni][r] = 0.f;

        // ---- L1: y0 half of the GEMM (independent of h) ----
        if constexpr (!IS_L0) {
            const uint32_t ab = smb + AS_OFF + (uint32_t)cb * HB_BUFB;
            #pragma unroll
            for (int kc = 0; kc < 16; kc++) {
                uint32_t a0[4], a1[4], bb[4];
                ldsm4(a0, ab + aoff0 + kc * 32u);
                ldsm4(a1, ab + aoff1 + kc * 32u);
                ldsm4(bb, bAddr + kc * 32u);
                mma16816(acc[0][0], a0, bb[0], bb[1]);
                mma16816(acc[0][1], a0, bb[2], bb[3]);
                mma16816(acc[1][0], a1, bb[0], bb[1]);
                mma16816(acc[1][1], a1, bb[2], bb[3]);
            }
        }

        // ---- wait for h_t (pushed into our local hbuf by all 8 CTAs) ----
        if (t > 0) {
            const uint32_t par = (uint32_t)(((t >> 1) + ((t & 1) ^ 1)) & 1);
            mbar_wait(mb_local + cb * 8, par);
        }

        // ---- h half of the GEMM ----
        {
            const uint32_t hb = smb + HB_OFF + (uint32_t)cb * HB_BUFB;
            #pragma unroll
            for (int kc = 0; kc < 16; kc++) {
                uint32_t a0[4], a1[4];
                ldsm4(a0, hb + aoff0 + kc * 32u);
                ldsm4(a1, hb + aoff1 + kc * 32u);
                if constexpr (IS_L0) {
                    mma16816(acc[0][0], a0, bw[0][kc][0], bw[0][kc][1]);
                    mma16816(acc[0][1], a0, bw[1][kc][0], bw[1][kc][1]);
                    mma16816(acc[1][0], a1, bw[0][kc][0], bw[0][kc][1]);
                    mma16816(acc[1][1], a1, bw[1][kc][0], bw[1][kc][1]);
                } else {
                    uint32_t bb[4];
                    ldsm4(bb, bAddr + (16 + kc) * 32u);
                    mma16816(acc[0][0], a0, bb[0], bb[1]);
                    mma16816(acc[0][1], a0, bb[2], bb[3]);
                    mma16816(acc[1][0], a1, bb[0], bb[1]);
                    mma16816(acc[1][1], a1, bb[2], bb[3]);
                }
            }
        }

        // ---- dump accumulators so each thread owns whole units ----
        #pragma unroll
        for (int mi = 0; mi < 2; mi++)
            #pragma unroll
            for (int ni = 0; ni < 2; ni++) {
                float* gp = Gs + (mi * 16 + gid) * GS + warp * 16 + ni * 8 + tig * 2;
                *(float2*)gp            = make_float2(acc[mi][ni][0], acc[mi][ni][1]);
                *(float2*)(gp + 8 * GS) = make_float2(acc[mi][ni][2], acc[mi][ni][3]);
            }
        __syncthreads();

        // ---- elementwise: 4 hidden units of one batch row ----
        float hv[4];
        float xv = IS_L0 ? xs[cb * MT + m] : 0.f;
        #pragma unroll
        for (int e = 0; e < 4; e++) {
            int nl = (ubase + e) * 4;
            const float4 gv = *(const float4*)(Gs + m * GS + nl);
            float pi = gv.x + bias_s[nl + 0];
            float pf = gv.y + bias_s[nl + 1];
            float pg = gv.z + bias_s[nl + 2];
            float po = gv.w + bias_s[nl + 3];
            if constexpr (IS_L0) {
                pi += xv * wx_s[nl + 0];
                pf += xv * wx_s[nl + 1];
                pg += xv * wx_s[nl + 2];
                po += xv * wx_s[nl + 3];
            }
            float ig = sig_hw(pi), fg = sig_hw(pf);
            float gg = tanh_hw(pg), og = sig_hw(po);
            float c  = fg * creg[e] + ig * gg;
            creg[e]  = c;
            hv[e]    = og * tanh_hw(c);
        }

        // ---- push h_{t+1} into all 8 cluster CTAs' smem (incl. self) ----
        __half2 p01 = __floats2half2_rn(hv[0], hv[1]);
        __half2 p23 = __floats2half2_rn(hv[2], hv[3]);
        uint2 pk = make_uint2(*(uint32_t*)&p01, *(uint32_t*)&p23);
        if (t + 1 < T_) {
            const uint64_t pv = ((uint64_t)pk.y << 32) | (uint64_t)pk.x;
            const uint32_t boff = (uint32_t)nb * HB_BUFB;
            const uint32_t moff = (uint32_t)nb * 8u;
            #pragma unroll
            for (int r = 0; r < CLUSTER; r++)
                st_async_u64(dstB[r] + boff, pv, mbB[r] + moff);
        }
        if constexpr (IS_L0) {
            *(uint2*)(g_y0 + ((size_t)t * B_ + b0 + m) * H_ + j0 + ubase) = pk;
        }
        if (t == T_ - 1) {
            size_t oidx = ((size_t)layer_idx * B_ + (b0 + m)) * H_ + j0 + ubase;
            *(float4*)(out + oidx) = make_float4(hv[0], hv[1], hv[2], hv[3]);
            *(float4*)(out + (size_t)2 * B_ * H_ + oidx) =
                make_float4(creg[0], creg[1], creg[2], creg[3]);
        }

        __syncthreads();   // guards Gs reuse; L0: orders y0 STGs before red

        if constexpr (IS_L0) {
            if (tid == 0) { __threadfence(); red_add_rel(g_ctr0 + grp); }
            if (tid < MT && t + 1 < T_)
                xs[nb * MT + tid] = x[(size_t)(b0 + tid) * T_ + (t + 1)];
        } else {
            if (t + 1 < T_) {
                if (tid == 0) {
                    const unsigned need = (unsigned)NTILE * (unsigned)(t + 2);
                    while (ld_acq(g_ctr0 + grp) < need) { }
                }
                __syncthreads();
                int row = tid >> 3, seg = tid & 7;
                const uint4* src = (const uint4*)(g_y0 +
                    ((size_t)(t + 1) * B_ + b0 + row) * H_ + seg * 32);
                uint4* dst = (uint4*)(As + (size_t)nb * HB_HALF + row * RSH + seg * 32);
                #pragma unroll
                for (int i = 0; i < 4; i++) dst[i] = src[i];
                __syncthreads();
            }
        }
    }
}

__global__ void __cluster_dims__(CLUSTER, 1, 1) __launch_bounds__(THREADS, 1)
lstm_fused_kernel(const float* __restrict__ x,
                  const float* __restrict__ Wih0, const float* __restrict__ Whh0,
                  const float* __restrict__ bih0, const float* __restrict__ bhh0,
                  const float* __restrict__ Wih1, const float* __restrict__ Whh1,
                  const float* __restrict__ bih1, const float* __restrict__ bhh1,
                  float* __restrict__ out) {
    if (blockIdx.z == 0)
        run_layer<true >(x, Wih0, Whh0, bih0, bhh0, out, 0);
    else
        run_layer<false>(nullptr, Wih1, Whh1, bih1, bhh1, out, 1);
}

extern "C" void kernel_launch(void* const* d_in, const int* in_sizes, int n_in,
                              void* d_out, int out_size) {
    (void)in_sizes; (void)n_in; (void)out_size;
    const float* x    = (const float*)d_in[0];
    const float* Wih0 = (const float*)d_in[1];
    const float* Whh0 = (const float*)d_in[2];
    const float* bih0 = (const float*)d_in[3];
    const float* bhh0 = (const float*)d_in[4];
    const float* Wih1 = (const float*)d_in[5];
    const float* Whh1 = (const float*)d_in[6];
    const float* bih1 = (const float*)d_in[7];
    const float* bhh1 = (const float*)d_in[8];
    float* out = (float*)d_out;

    cudaFuncSetAttribute((const void*)&lstm_fused_kernel,
                         cudaFuncAttributeMaxDynamicSharedMemorySize, SMEM_TOTAL);

    init_kernel<<<1, 32>>>();

    dim3 grid(NTILE, NGROUP, 2);
    lstm_fused_kernel<<<grid, THREADS, SMEM_TOTAL>>>(
        x, Wih0, Whh0, bih0, bhh0, Wih1, Whh1, bih1, bhh1, out);
}

// round 6
// speedup vs baseline: 1.6262x; 1.6262x over previous
#include <cuda_runtime.h>
#include <cuda_fp16.h>
#include <cstdint>

#define B_  256
#define T_  1024
#define H_  256

#define MT 32       // batch rows per group
#define NT 128      // permuted gate cols per CTA (32 hidden units x 4 gates)
#define NGROUP 8
#define NTILE  8
#define THREADS 256

#define RS0 264     // L0 A row stride (halfs): K=256 + pad
#define RS1 520     // L1 A row stride (halfs): K=512 concat [y0|h] + pad
#define WRS 264     // L1 y0-half weight row stride (halfs)
#define GS  132     // gate dump row stride (floats)

// ---- dynamic smem layout (bytes), sized for L1 (worst case) ----
#define AS_OFF   0
#define WS_OFF   (2 * MT * RS1 * 2)            // 66560
#define GS_OFF   (WS_OFF + NT * WRS * 2)       // 134144
#define BIAS_OFF (GS_OFF + MT * GS * 4)        // 151040
#define WX_OFF   (BIAS_OFF + NT * 4)           // 151552
#define XS_OFF   (WX_OFF + NT * 4)             // 152064
#define SMEM_TOTAL (XS_OFF + 2 * MT * 4)       // 152320

// -------- persistent device scratch (no allocations allowed) --------
__device__ __half   g_y0[(size_t)T_ * B_ * H_];            // [T][B][H]
// h slices: [layer][buf][grp][producer][row*32+unit], 2KB contiguous per block
__device__ __half   g_hs[2][2][NGROUP][NTILE][MT * 32];
__device__ unsigned g_flag[2][NGROUP][NTILE][32];          // 128B-strided monotonic flags

__global__ void init_kernel() {
    int i = threadIdx.x;
    if (i < 2 * NGROUP * NTILE) ((unsigned*)g_flag)[i * 32] = 0u;
}

// -------- helpers --------
__device__ __forceinline__ uint32_t smem_u32(const void* p) {
    return (uint32_t)__cvta_generic_to_shared(p);
}
__device__ __forceinline__ unsigned ld_acq(const unsigned* p) {
    unsigned v;
    asm volatile("ld.acquire.gpu.global.u32 %0, [%1];" : "=r"(v) : "l"(p) : "memory");
    return v;
}
__device__ __forceinline__ void st_rel(unsigned* p, unsigned v) {
    asm volatile("st.release.gpu.global.u32 [%0], %1;" :: "l"(p), "r"(v) : "memory");
}
__device__ __forceinline__ float tanh_hw(float x) {
    float y;
    asm("tanh.approx.f32 %0, %1;" : "=f"(y) : "f"(x));
    return y;
}
__device__ __forceinline__ float sig_hw(float x) {
    return fmaf(0.5f, tanh_hw(0.5f * x), 0.5f);
}
__device__ __forceinline__ void mma16816(float* d, const uint32_t* a, uint32_t b0, uint32_t b1) {
    asm volatile(
        "mma.sync.aligned.m16n8k16.row.col.f32.f16.f16.f32 "
        "{%0,%1,%2,%3}, {%4,%5,%6,%7}, {%8,%9}, {%0,%1,%2,%3};\n"
        : "+f"(d[0]), "+f"(d[1]), "+f"(d[2]), "+f"(d[3])
        : "r"(a[0]), "r"(a[1]), "r"(a[2]), "r"(a[3]), "r"(b0), "r"(b1));
}
__device__ __forceinline__ void ldsm4(uint32_t* r, uint32_t addr) {
    asm volatile("ldmatrix.sync.aligned.m8n8.x4.shared.b16 {%0,%1,%2,%3}, [%4];"
        : "=r"(r[0]), "=r"(r[1]), "=r"(r[2]), "=r"(r[3]) : "r"(addr));
}

// ====================================================================
// One persistent LSTM layer, 8 CTAs per batch group, exchange via L2.
// Gate cols permuted: perm col n -> original row (n&3)*H + (n>>2).
//  - producer publishes its 2KB h-slice as ONE contiguous block, then
//    st.release of a per-producer monotonic flag (= t+1).
//  - consumer warp w polls producer w's flag (parallel across warps),
//    copies the block into smem (fully coalesced both sides).
//  - h-GEMM weights live in registers for BOTH layers (64 regs).
//  - L1 runs its y0-half GEMM (A prefetched last step, W in smem)
//    BEFORE the h wait, hiding exchange latency.
//  - t=0: h == 0 so the h-GEMM is skipped entirely (no zero-init).
// ====================================================================
template <int RS, bool IS_L0>
__device__ __forceinline__ void run_layer(const float* __restrict__ x,
                                          const float* __restrict__ Wih,
                                          const float* __restrict__ Whh,
                                          const float* __restrict__ bih,
                                          const float* __restrict__ bhh,
                                          float* __restrict__ out,
                                          int layer_idx) {
    constexpr int L    = IS_L0 ? 0 : 1;
    constexpr int HCOL = IS_L0 ? 0 : 512;   // byte offset of h region within an A row

    extern __shared__ char sm[];
    const uint32_t smb = smem_u32(sm);
    float* Gs     = (float*)(sm + GS_OFF);
    float* bias_s = (float*)(sm + BIAS_OFF);
    float* wx_s   = (float*)(sm + WX_OFF);
    float* xs     = (float*)(sm + XS_OFF);
    __half* Ws    = (__half*)(sm + WS_OFF);

    const int tid  = threadIdx.x;
    const int lane = tid & 31, warp = tid >> 5;
    const int gid  = lane >> 2, tig = lane & 3;
    const int ntile = blockIdx.x, grp = blockIdx.y;
    const int n0 = ntile * NT;
    const int b0 = grp * MT;
    const int j0 = n0 >> 2;

    // ---- one-time: bias (+ scalar input weight for L0) ----
    if (tid < NT) {
        int n_g = n0 + tid;
        int p   = (n_g & 3) * H_ + (n_g >> 2);
        bias_s[tid] = bih[p] + bhh[p];
        if (IS_L0) wx_s[tid] = Wih[p];
    }

    // ---- one-time: h-half weights (Whh) into registers ----
    uint32_t bw[2][16][2];
    #pragma unroll
    for (int ni = 0; ni < 2; ni++) {
        int n_g = n0 + warp * 16 + ni * 8 + gid;
        int p   = (n_g & 3) * H_ + (n_g >> 2);
        const float* wr = Whh + (size_t)p * H_;
        #pragma unroll
        for (int kc = 0; kc < 16; kc++) {
            int k = kc * 16 + tig * 2;
            __half2 h01 = __floats2half2_rn(wr[k], wr[k + 1]);
            __half2 h89 = __floats2half2_rn(wr[k + 8], wr[k + 9]);
            bw[ni][kc][0] = *(uint32_t*)&h01;
            bw[ni][kc][1] = *(uint32_t*)&h89;
        }
    }

    if constexpr (IS_L0) {
        if (tid < MT) xs[tid] = x[(size_t)(b0 + tid) * T_];
    } else {
        // y0-half weights (Wih1, K=256) into smem
        for (int idx = tid; idx < NT * H_; idx += THREADS) {
            int nl = idx >> 8, k = idx & 255;
            int n_g = n0 + nl;
            int p   = (n_g & 3) * H_ + (n_g >> 2);
            Ws[nl * WRS + k] = __float2half_rn(Wih[(size_t)p * H_ + k]);
        }
        // prologue: wait for y0(0), cooperative coalesced load into A buf 0
        { const unsigned* f = &g_flag[0][grp][warp][0];
          while (ld_acq(f) < 1u) { } }
        __syncthreads();
        const char* src = (const char*)(g_y0 + (size_t)b0 * H_);
        #pragma unroll
        for (int i = 0; i < 4; i++) {
            int off = tid * 16 + i * 4096;
            int row = off >> 9, colb = off & 511;
            *(uint4*)(sm + AS_OFF + row * (RS * 2) + colb) = *(const uint4*)(src + off);
        }
    }
    __syncthreads();

    // ---- ldsm fragment byte offsets within an A buffer ----
    const uint32_t aoff0 = (uint32_t)(((lane & 15) * RS + ((lane >> 4) & 1) * 8) * 2);
    const uint32_t aoff1 = aoff0 + (uint32_t)(16 * RS * 2);
    uint32_t bAddr = 0;
    if constexpr (!IS_L0) {
        int rB = warp * 16 + (lane & 7) + ((lane & 16) ? 8 : 0);
        int cB = (lane & 8) ? 8 : 0;
        bAddr = smb + WS_OFF + (uint32_t)((rB * WRS + cB) * 2);
    }

    const int m     = tid >> 3;
    const int ubase = (tid & 7) * 4;
    float creg[4] = {0.f, 0.f, 0.f, 0.f};

    for (int t = 0; t < T_; ++t) {
        const int cb = t & 1, nb = cb ^ 1;
        const uint32_t baseA = smb + AS_OFF + (uint32_t)cb * (MT * RS * 2);

        float acc[2][2][4];
        #pragma unroll
        for (int mi = 0; mi < 2; mi++)
            #pragma unroll
            for (int ni = 0; ni < 2; ni++)
                #pragma unroll
                for (int r = 0; r < 4; r++) acc[mi][ni][r] = 0.f;

        // ---- L1: y0-half GEMM (independent of h; hides exchange) ----
        if constexpr (!IS_L0) {
            #pragma unroll
            for (int kc = 0; kc < 16; kc++) {
                uint32_t a0[4], a1[4], bb[4];
                ldsm4(a0, baseA + aoff0 + kc * 32u);
                ldsm4(a1, baseA + aoff1 + kc * 32u);
                ldsm4(bb, bAddr + kc * 32u);
                mma16816(acc[0][0], a0, bb[0], bb[1]);
                mma16816(acc[0][1], a0, bb[2], bb[3]);
                mma16816(acc[1][0], a1, bb[0], bb[1]);
                mma16816(acc[1][1], a1, bb[2], bb[3]);
            }
        }

        if (t > 0) {
            // ---- h exchange: warp w waits on producer w, copies its 2KB block ----
            {
                const unsigned* f = &g_flag[L][grp][warp][0];
                while (ld_acq(f) < (unsigned)t) { }
                const char* hsrc = (const char*)g_hs[L][cb][grp][warp];
                char* dstb = sm + AS_OFF + cb * (MT * RS * 2) + HCOL + warp * 64;
                #pragma unroll
                for (int i = 0; i < 4; i++) {
                    int off = lane * 16 + i * 512;          // contiguous per instr
                    int row = off >> 6, ub = off & 63;      // block row = 64B
                    *(uint4*)(dstb + row * (RS * 2) + ub) = *(const uint4*)(hsrc + off);
                }
            }
            __syncthreads();

            // ---- h-half GEMM, weights in registers ----
            #pragma unroll
            for (int kc = 0; kc < 16; kc++) {
                uint32_t a0[4], a1[4];
                ldsm4(a0, baseA + HCOL + aoff0 + kc * 32u);
                ldsm4(a1, baseA + HCOL + aoff1 + kc * 32u);
                mma16816(acc[0][0], a0, bw[0][kc][0], bw[0][kc][1]);
                mma16816(acc[0][1], a0, bw[1][kc][0], bw[1][kc][1]);
                mma16816(acc[1][0], a1, bw[0][kc][0], bw[0][kc][1]);
                mma16816(acc[1][1], a1, bw[1][kc][0], bw[1][kc][1]);
            }
        }

        // ---- dump accumulators so each thread owns whole units ----
        #pragma unroll
        for (int mi = 0; mi < 2; mi++)
            #pragma unroll
            for (int ni = 0; ni < 2; ni++) {
                float* gp = Gs + (mi * 16 + gid) * GS + warp * 16 + ni * 8 + tig * 2;
                *(float2*)gp            = make_float2(acc[mi][ni][0], acc[mi][ni][1]);
                *(float2*)(gp + 8 * GS) = make_float2(acc[mi][ni][2], acc[mi][ni][3]);
            }
        __syncthreads();

        // ---- elementwise: 4 hidden units of one batch row ----
        float hv[4];
        float xv = IS_L0 ? xs[cb * MT + m] : 0.f;
        #pragma unroll
        for (int e = 0; e < 4; e++) {
            int nl = (ubase + e) * 4;
            const float4 gv = *(const float4*)(Gs + m * GS + nl);
            float pi = gv.x + bias_s[nl + 0];
            float pf = gv.y + bias_s[nl + 1];
            float pg = gv.z + bias_s[nl + 2];
            float po = gv.w + bias_s[nl + 3];
            if constexpr (IS_L0) {
                pi += xv * wx_s[nl + 0];
                pf += xv * wx_s[nl + 1];
                pg += xv * wx_s[nl + 2];
                po += xv * wx_s[nl + 3];
            }
            float ig = sig_hw(pi), fg = sig_hw(pf);
            float gg = tanh_hw(pg), og = sig_hw(po);
            float c  = fg * creg[e] + ig * gg;
            creg[e]  = c;
            hv[e]    = og * tanh_hw(c);
        }

        // ---- publish h(t+1) slice (contiguous 2KB block), y0 for L0 ----
        __half2 p01 = __floats2half2_rn(hv[0], hv[1]);
        __half2 p23 = __floats2half2_rn(hv[2], hv[3]);
        uint2 pk = make_uint2(*(uint32_t*)&p01, *(uint32_t*)&p23);
        if (t + 1 < T_)
            *(uint2*)&g_hs[L][nb][grp][ntile][m * 32 + ubase] = pk;
        if constexpr (IS_L0)
            *(uint2*)(g_y0 + ((size_t)t * B_ + b0 + m) * H_ + j0 + ubase) = pk;
        if (t == T_ - 1) {
            size_t oidx = ((size_t)layer_idx * B_ + (b0 + m)) * H_ + j0 + ubase;
            *(float4*)(out + oidx) = make_float4(hv[0], hv[1], hv[2], hv[3]);
            *(float4*)(out + (size_t)2 * B_ * H_ + oidx) =
                make_float4(creg[0], creg[1], creg[2], creg[3]);
        }

        __syncthreads();   // STGs done by all threads; also guards Gs/xs reuse
        if (tid == 0) {
            __threadfence();
            st_rel(&g_flag[L][grp][ntile][0], (unsigned)(t + 1));
        }

        // ---- prefetch for next step (off the exchange critical path) ----
        if constexpr (IS_L0) {
            if (tid < MT && t + 1 < T_)
                xs[nb * MT + tid] = x[(size_t)(b0 + tid) * T_ + (t + 1)];
        } else {
            if (t + 1 < T_) {
                { const unsigned* f = &g_flag[0][grp][warp][0];
                  while (ld_acq(f) < (unsigned)(t + 2)) { } }
                __syncthreads();
                const char* src = (const char*)(g_y0 + ((size_t)(t + 1) * B_ + b0) * H_);
                char* dstb = sm + AS_OFF + nb * (MT * RS * 2);
                #pragma unroll
                for (int i = 0; i < 4; i++) {
                    int off = tid * 16 + i * 4096;
                    int row = off >> 9, colb = off & 511;
                    *(uint4*)(dstb + row * (RS * 2) + colb) = *(const uint4*)(src + off);
                }
                __syncthreads();
            }
        }
    }
}

__global__ void __launch_bounds__(THREADS, 1)
lstm_fused_kernel(const float* __restrict__ x,
                  const float* __restrict__ Wih0, const float* __restrict__ Whh0,
                  const float* __restrict__ bih0, const float* __restrict__ bhh0,
                  const float* __restrict__ Wih1, const float* __restrict__ Whh1,
                  const float* __restrict__ bih1, const float* __restrict__ bhh1,
                  float* __restrict__ out) {
    if (blockIdx.z == 0)
        run_layer<RS0, true >(x, Wih0, Whh0, bih0, bhh0, out, 0);
    else
        run_layer<RS1, false>(nullptr, Wih1, Whh1, bih1, bhh1, out, 1);
}

extern "C" void kernel_launch(void* const* d_in, const int* in_sizes, int n_in,
                              void* d_out, int out_size) {
    (void)in_sizes; (void)n_in; (void)out_size;
    const float* x    = (const float*)d_in[0];
    const float* Wih0 = (const float*)d_in[1];
    const float* Whh0 = (const float*)d_in[2];
    const float* bih0 = (const float*)d_in[3];
    const float* bhh0 = (const float*)d_in[4];
    const float* Wih1 = (const float*)d_in[5];
    const float* Whh1 = (const float*)d_in[6];
    const float* bih1 = (const float*)d_in[7];
    const float* bhh1 = (const float*)d_in[8];
    float* out = (float*)d_out;

    cudaFuncSetAttribute((const void*)&lstm_fused_kernel,
                         cudaFuncAttributeMaxDynamicSharedMemorySize, SMEM_TOTAL);

    init_kernel<<<1, 128>>>();

    dim3 grid(NTILE, NGROUP, 2);
    lstm_fused_kernel<<<grid, THREADS, SMEM_TOTAL>>>(
        x, Wih0, Whh0, bih0, bhh0, Wih1, Whh1, bih1, bhh1, out);
}

// round 7
// speedup vs baseline: 1.6637x; 1.0230x over previous
#include <cuda_runtime.h>
#include <cuda_fp16.h>
#include <cstdint>

#define B_  256
#define T_  1024
#define H_  256

#define MT 32       // batch rows per group
#define NT 128      // permuted gate cols per CTA (32 hidden units x 4 gates)
#define NGROUP 8
#define NTILE  8
#define THREADS 256

#define WRS 264     // L1 y0-half weight row stride (halfs)
#define GS  132     // gate dump row stride (floats)
#define BLKB 2560   // bytes per producer block: 32 rows x 80B (ldsm conflict-free)
#define GBUF 20480  // 8 blocks = full 32x256 A tile

// ---- dynamic smem layout (bytes) ----
#define AS_Y     0                      // [2][GBUF] y0 tiles (L1)
#define AS_H     40960                  // [2][GBUF] h tiles
#define WS_OFF   81920                  // [NT][WRS] halfs (L1 y0 weights)
#define GS_OFF   149504                 // [MT][GS] floats
#define BIAS_OFF 166400
#define WX_OFF   166912
#define XS_OFF   167424                 // [2][MT] floats
#define MBAR_OFF 167680                 // H: buf*16+half*8 ; Y: +32 + buf*8
#define SMEM_TOTAL 167744

// -------- persistent device scratch --------
// blocked layout: [..][grp][producer][row*40 + unit] halfs (80B rows)
__device__ __align__(16) __half g_y0[T_][NGROUP][NTILE][BLKB / 2];
__device__ __align__(16) __half g_h1[2][NGROUP][NTILE][BLKB / 2];
__device__ unsigned g_flag[2][NGROUP][NTILE][32];   // 128B-strided monotonic flags

__global__ void init_kernel() {
    int i = threadIdx.x;
    if (i < 2 * NGROUP * NTILE) ((unsigned*)g_flag)[i * 32] = 0u;
}

// -------- helpers --------
__device__ __forceinline__ uint32_t smem_u32(const void* p) {
    return (uint32_t)__cvta_generic_to_shared(p);
}
__device__ __forceinline__ unsigned ld_acq(const unsigned* p) {
    unsigned v;
    asm volatile("ld.acquire.gpu.global.u32 %0, [%1];" : "=r"(v) : "l"(p) : "memory");
    return v;
}
__device__ __forceinline__ void st_rel(unsigned* p, unsigned v) {
    asm volatile("st.release.gpu.global.u32 [%0], %1;" :: "l"(p), "r"(v) : "memory");
}
__device__ __forceinline__ float tanh_hw(float x) {
    float y;
    asm("tanh.approx.f32 %0, %1;" : "=f"(y) : "f"(x));
    return y;
}
__device__ __forceinline__ float sig_hw(float x) {
    return fmaf(0.5f, tanh_hw(0.5f * x), 0.5f);
}
__device__ __forceinline__ void mma16816(float* d, const uint32_t* a, uint32_t b0, uint32_t b1) {
    asm volatile(
        "mma.sync.aligned.m16n8k16.row.col.f32.f16.f16.f32 "
        "{%0,%1,%2,%3}, {%4,%5,%6,%7}, {%8,%9}, {%0,%1,%2,%3};\n"
        : "+f"(d[0]), "+f"(d[1]), "+f"(d[2]), "+f"(d[3])
        : "r"(a[0]), "r"(a[1]), "r"(a[2]), "r"(a[3]), "r"(b0), "r"(b1));
}
__device__ __forceinline__ void ldsm4(uint32_t* r, uint32_t addr) {
    asm volatile("ldmatrix.sync.aligned.m8n8.x4.shared.b16 {%0,%1,%2,%3}, [%4];"
        : "=r"(r[0]), "=r"(r[1]), "=r"(r[2]), "=r"(r[3]) : "r"(addr));
}
__device__ __forceinline__ void bulk_g2s(uint32_t dst, const void* src,
                                         uint32_t bytes, uint32_t mbar) {
    asm volatile(
        "cp.async.bulk.shared::cluster.global.mbarrier::complete_tx::bytes "
        "[%0], [%1], %2, [%3];"
        :: "r"(dst), "l"(src), "r"(bytes), "r"(mbar) : "memory");
}
__device__ __forceinline__ void mbar_init(uint32_t a, uint32_t cnt) {
    asm volatile("mbarrier.init.shared.b64 [%0], %1;" :: "r"(a), "r"(cnt) : "memory");
}
__device__ __forceinline__ void mbar_expect(uint32_t a, uint32_t bytes) {
    asm volatile("mbarrier.arrive.expect_tx.shared.b64 _, [%0], %1;"
                 :: "r"(a), "r"(bytes) : "memory");
}
__device__ __forceinline__ void mbar_wait(uint32_t a, uint32_t par) {
    uint32_t done = 0;
    while (!done) {
        asm volatile(
            "{\n\t.reg .pred p;\n\t"
            "mbarrier.try_wait.parity.acquire.cta.shared::cta.b64 p, [%1], %2, 0x989680;\n\t"
            "selp.b32 %0, 1, 0, p;\n\t}"
            : "=r"(done) : "r"(a), "r"(par) : "memory");
    }
}

// ====================================================================
// Persistent LSTM layer, 8 CTAs per batch group, L2 exchange via
// cp.async.bulk into ldsm-ready blocked smem (80B rows, conflict-free).
//  - producer publishes its 2.5KB blocked h-slice + st.release flag.
//  - consumer warp w: lane0 polls producer w's flag, issues ONE bulk;
//    two half-mbarriers let GEMM on blocks 0-3 overlap arrival of 4-7.
//  - L0's h buffer IS g_y0[t-1] (published once, consumed by both layers).
//  - L1 issues h bulks first, then runs its y0-half GEMM while they fly.
// ====================================================================
template <bool IS_L0>
__device__ __forceinline__ void run_layer(const float* __restrict__ x,
                                          const float* __restrict__ Wih,
                                          const float* __restrict__ Whh,
                                          const float* __restrict__ bih,
                                          const float* __restrict__ bhh,
                                          float* __restrict__ out,
                                          int layer_idx) {
    constexpr int L = IS_L0 ? 0 : 1;

    extern __shared__ char sm[];
    const uint32_t smb = smem_u32(sm);
    float*  Gs     = (float*)(sm + GS_OFF);
    float*  bias_s = (float*)(sm + BIAS_OFF);
    float*  wx_s   = (float*)(sm + WX_OFF);
    float*  xs     = (float*)(sm + XS_OFF);
    __half* Ws     = (__half*)(sm + WS_OFF);
    const uint32_t mbH = smb + MBAR_OFF;        // [buf][half] 8B each
    const uint32_t mbY = smb + MBAR_OFF + 32;   // [buf]

    const int tid  = threadIdx.x;
    const int lane = tid & 31, warp = tid >> 5;
    const int gid  = lane >> 2, tig = lane & 3;
    const int ntile = blockIdx.x, grp = blockIdx.y;
    const int n0 = ntile * NT;
    const int b0 = grp * MT;
    const int j0 = n0 >> 2;

    // ---- mbarrier init (count=1: tid0's arrive.expect each phase) ----
    if (tid == 0) {
        mbar_init(mbH + 0, 1);  mbar_init(mbH + 8, 1);
        mbar_init(mbH + 16, 1); mbar_init(mbH + 24, 1);
        mbar_init(mbY + 0, 1);  mbar_init(mbY + 8, 1);
    }
    __syncthreads();

    // ---- one-time: bias (+ scalar input weight for L0) ----
    if (tid < NT) {
        int n_g = n0 + tid;
        int p   = (n_g & 3) * H_ + (n_g >> 2);
        bias_s[tid] = bih[p] + bhh[p];
        if (IS_L0) wx_s[tid] = Wih[p];
    }

    // ---- one-time: h-half weights (Whh) into registers, k = unit idx ----
    uint32_t bw[2][16][2];
    #pragma unroll
    for (int ni = 0; ni < 2; ni++) {
        int n_g = n0 + warp * 16 + ni * 8 + gid;
        int p   = (n_g & 3) * H_ + (n_g >> 2);
        const float* wr = Whh + (size_t)p * H_;
        #pragma unroll
        for (int kc = 0; kc < 16; kc++) {
            int k = kc * 16 + tig * 2;
            __half2 h01 = __floats2half2_rn(wr[k], wr[k + 1]);
            __half2 h89 = __floats2half2_rn(wr[k + 8], wr[k + 9]);
            bw[ni][kc][0] = *(uint32_t*)&h01;
            bw[ni][kc][1] = *(uint32_t*)&h89;
        }
    }

    if constexpr (IS_L0) {
        if (tid < MT) xs[tid] = x[(size_t)(b0 + tid) * T_];
        __syncthreads();
    } else {
        // y0-half weights (Wih1, K=256) into smem, k = unit idx
        for (int idx = tid; idx < NT * H_; idx += THREADS) {
            int nl = idx >> 8, k = idx & 255;
            int n_g = n0 + nl;
            int p   = (n_g & 3) * H_ + (n_g >> 2);
            Ws[nl * WRS + k] = __float2half_rn(Wih[(size_t)p * H_ + k]);
        }
        __syncthreads();
        if (tid == 0) mbar_expect(mbY + 0, GBUF);
        __syncthreads();
        if (lane == 0) {
            while (ld_acq(&g_flag[0][grp][warp][0]) < 1u) { }
            bulk_g2s(smb + AS_Y + warp * BLKB, &g_y0[0][grp][warp][0], BLKB, mbY + 0);
        }
    }

    // ---- per-lane ldsm byte offset within a blocked A tile ----
    const uint32_t aoffB = (uint32_t)((lane & 15) * 80 + ((lane >> 4) & 1) * 16);
    uint32_t bAddr = 0;
    if constexpr (!IS_L0) {
        int rB = warp * 16 + (lane & 7) + ((lane & 16) ? 8 : 0);
        int cB = (lane & 8) ? 8 : 0;
        bAddr = smb + WS_OFF + (uint32_t)((rB * WRS + cB) * 2);
    }

    const int m     = tid >> 3;
    const int ubase = (tid & 7) * 4;
    float creg[4] = {0.f, 0.f, 0.f, 0.f};

    for (int t = 0; t < T_; ++t) {
        const int cb = t & 1, nb = cb ^ 1;
        const uint32_t parh = (uint32_t)(((t >> 1) + ((t & 1) ^ 1)) & 1);
        const uint32_t pary = (uint32_t)((t >> 1) & 1);
        const uint32_t hbase = smb + AS_H + (uint32_t)cb * GBUF;

        // ---- issue h bulks first (copies fly during y0-GEMM) ----
        if (t > 0 && lane == 0) {
            while (ld_acq(&g_flag[L][grp][warp][0]) < (unsigned)t) { }
            const void* src = IS_L0 ? (const void*)&g_y0[t - 1][grp][warp][0]
                                    : (const void*)&g_h1[cb][grp][warp][0];
            bulk_g2s(hbase + warp * BLKB, src, BLKB, mbH + cb * 16 + (warp >> 2) * 8);
        }

        float acc[2][2][4];
        #pragma unroll
        for (int mi = 0; mi < 2; mi++)
            #pragma unroll
            for (int ni = 0; ni < 2; ni++)
                #pragma unroll
                for (int r = 0; r < 4; r++) acc[mi][ni][r] = 0.f;

        // ---- L1: y0-half GEMM (independent of h) ----
        if constexpr (!IS_L0) {
            mbar_wait(mbY + cb * 8, pary);
            const uint32_t ybase = smb + AS_Y + (uint32_t)cb * GBUF;
            #pragma unroll
            for (int kc = 0; kc < 16; kc++) {
                uint32_t a0[4], a1[4], bb[4];
                const uint32_t ad = ybase + (kc >> 1) * BLKB + (kc & 1) * 32 + aoffB;
                ldsm4(a0, ad);
                ldsm4(a1, ad + 1280);
                ldsm4(bb, bAddr + kc * 32u);
                mma16816(acc[0][0], a0, bb[0], bb[1]);
                mma16816(acc[0][1], a0, bb[2], bb[3]);
                mma16816(acc[1][0], a1, bb[0], bb[1]);
                mma16816(acc[1][1], a1, bb[2], bb[3]);
            }
        }

        // ---- h-half GEMM, two halves overlapped with arrival ----
        if (t > 0) {
            mbar_wait(mbH + cb * 16 + 0, parh);
            #pragma unroll
            for (int kc = 0; kc < 8; kc++) {
                uint32_t a0[4], a1[4];
                const uint32_t ad = hbase + (kc >> 1) * BLKB + (kc & 1) * 32 + aoffB;
                ldsm4(a0, ad);
                ldsm4(a1, ad + 1280);
                mma16816(acc[0][0], a0, bw[0][kc][0], bw[0][kc][1]);
                mma16816(acc[0][1], a0, bw[1][kc][0], bw[1][kc][1]);
                mma16816(acc[1][0], a1, bw[0][kc][0], bw[0][kc][1]);
                mma16816(acc[1][1], a1, bw[1][kc][0], bw[1][kc][1]);
            }
            mbar_wait(mbH + cb * 16 + 8, parh);
            #pragma unroll
            for (int kc = 8; kc < 16; kc++) {
                uint32_t a0[4], a1[4];
                const uint32_t ad = hbase + (kc >> 1) * BLKB + (kc & 1) * 32 + aoffB;
                ldsm4(a0, ad);
                ldsm4(a1, ad + 1280);
                mma16816(acc[0][0], a0, bw[0][kc][0], bw[0][kc][1]);
                mma16816(acc[0][1], a0, bw[1][kc][0], bw[1][kc][1]);
                mma16816(acc[1][0], a1, bw[0][kc][0], bw[0][kc][1]);
                mma16816(acc[1][1], a1, bw[1][kc][0], bw[1][kc][1]);
            }
        }

        // ---- dump accumulators so each thread owns whole units ----
        #pragma unroll
        for (int mi = 0; mi < 2; mi++)
            #pragma unroll
            for (int ni = 0; ni < 2; ni++) {
                float* gp = Gs + (mi * 16 + gid) * GS + warp * 16 + ni * 8 + tig * 2;
                *(float2*)gp            = make_float2(acc[mi][ni][0], acc[mi][ni][1]);
                *(float2*)(gp + 8 * GS) = make_float2(acc[mi][ni][2], acc[mi][ni][3]);
            }
        __syncthreads();

        // ---- elementwise: 4 hidden units of one batch row ----
        float hv[4];
        float xv = IS_L0 ? xs[cb * MT + m] : 0.f;
        #pragma unroll
        for (int e = 0; e < 4; e++) {
            int nl = (ubase + e) * 4;
            const float4 gv = *(const float4*)(Gs + m * GS + nl);
            float pi = gv.x + bias_s[nl + 0];
            float pf = gv.y + bias_s[nl + 1];
            float pg = gv.z + bias_s[nl + 2];
            float po = gv.w + bias_s[nl + 3];
            if constexpr (IS_L0) {
                pi += xv * wx_s[nl + 0];
                pf += xv * wx_s[nl + 1];
                pg += xv * wx_s[nl + 2];
                po += xv * wx_s[nl + 3];
            }
            float ig = sig_hw(pi), fg = sig_hw(pf);
            float gg = tanh_hw(pg), og = sig_hw(po);
            float c  = fg * creg[e] + ig * gg;
            creg[e]  = c;
            hv[e]    = og * tanh_hw(c);
        }

        // ---- publish (blocked layout, 8B per thread) ----
        __half2 p01 = __floats2half2_rn(hv[0], hv[1]);
        __half2 p23 = __floats2half2_rn(hv[2], hv[3]);
        uint2 pk = make_uint2(*(uint32_t*)&p01, *(uint32_t*)&p23);
        if constexpr (IS_L0) {
            *(uint2*)&g_y0[t][grp][ntile][m * 40 + ubase] = pk;
        } else {
            if (t + 1 < T_)
                *(uint2*)&g_h1[nb][grp][ntile][m * 40 + ubase] = pk;
        }
        if (t == T_ - 1) {
            size_t oidx = ((size_t)layer_idx * B_ + (b0 + m)) * H_ + j0 + ubase;
            *(float4*)(out + oidx) = make_float4(hv[0], hv[1], hv[2], hv[3]);
            *(float4*)(out + (size_t)2 * B_ * H_ + oidx) =
                make_float4(creg[0], creg[1], creg[2], creg[3]);
        }

        // ---- expects for next step's buffers (before bulks can land) ----
        if (tid == 0 && t + 1 < T_) {
            mbar_expect(mbH + nb * 16 + 0, GBUF / 2);
            mbar_expect(mbH + nb * 16 + 8, GBUF / 2);
            if (!IS_L0) mbar_expect(mbY + nb * 8, GBUF);
        }
        __syncthreads();   // all publish STGs + expects done

        if (tid == 0) {
            if (IS_L0 || t + 1 < T_) {
                __threadfence();
                st_rel(&g_flag[L][grp][ntile][0], (unsigned)(t + 1));
            }
        }

        // ---- tail prefetch for next step ----
        if constexpr (IS_L0) {
            if (tid < MT && t + 1 < T_)
                xs[nb * MT + tid] = x[(size_t)(b0 + tid) * T_ + (t + 1)];
        } else {
            if (t + 1 < T_ && lane == 0) {
                while (ld_acq(&g_flag[0][grp][warp][0]) < (unsigned)(t + 2)) { }
                bulk_g2s(smb + AS_Y + (uint32_t)nb * GBUF + warp * BLKB,
                         &g_y0[t + 1][grp][warp][0], BLKB, mbY + nb * 8);
            }
        }
    }
}

__global__ void __launch_bounds__(THREADS, 1)
lstm_fused_kernel(const float* __restrict__ x,
                  const float* __restrict__ Wih0, const float* __restrict__ Whh0,
                  const float* __restrict__ bih0, const float* __restrict__ bhh0,
                  const float* __restrict__ Wih1, const float* __restrict__ Whh1,
                  const float* __restrict__ bih1, const float* __restrict__ bhh1,
                  float* __restrict__ out) {
    if (blockIdx.z == 0)
        run_layer<true >(x, Wih0, Whh0, bih0, bhh0, out, 0);
    else
        run_layer<false>(nullptr, Wih1, Whh1, bih1, bhh1, out, 1);
}

extern "C" void kernel_launch(void* const* d_in, const int* in_sizes, int n_in,
                              void* d_out, int out_size) {
    (void)in_sizes; (void)n_in; (void)out_size;
    const float* x    = (const float*)d_in[0];
    const float* Wih0 = (const float*)d_in[1];
    const float* Whh0 = (const float*)d_in[2];
    const float* bih0 = (const float*)d_in[3];
    const float* bhh0 = (const float*)d_in[4];
    const float* Wih1 = (const float*)d_in[5];
    const float* Whh1 = (const float*)d_in[6];
    const float* bih1 = (const float*)d_in[7];
    const float* bhh1 = (const float*)d_in[8];
    float* out = (float*)d_out;

    cudaFuncSetAttribute((const void*)&lstm_fused_kernel,
                         cudaFuncAttributeMaxDynamicSharedMemorySize, SMEM_TOTAL);

    init_kernel<<<1, 128>>>();

    dim3 grid(NTILE, NGROUP, 2);
    lstm_fused_kernel<<<grid, THREADS, SMEM_TOTAL>>>(
        x, Wih0, Whh0, bih0, bhh0, Wih1, Whh1, bih1, bhh1, out);
}